// round 6
// baseline (speedup 1.0000x reference)
#include <cuda_runtime.h>
#include <cuda_bf16.h>

// Problem constants
#define NN 10000
#define DD 128
#define NDSZ (NN * DD)

// Scratch (device globals; no allocations, no host symbol lookups)
__device__ float         g_qkvs[2 * NDSZ];   // Q (fp32), S (fp32)
__device__ __nv_bfloat16 g_kbf[NDSZ];        // K (bf16)
__device__ __nv_bfloat16 g_vbf[NDSZ];        // V (bf16)
__device__ float         g_h[NDSZ];          // hidden after layer 0
__device__ int           g_rowptr[NN + 1];

// ---------------------------------------------------------------------------
// row_ptr: edges sorted by src; rowptr[i] = first index with src[e] >= i
// ---------------------------------------------------------------------------
__global__ void build_rowptr_kernel(const int* __restrict__ src, int E) {
    int i = blockIdx.x * blockDim.x + threadIdx.x;
    if (i > NN) return;
    int lo = 0, hi = E;
    while (lo < hi) {
        int mid = (lo + hi) >> 1;
        if (src[mid] < i) lo = mid + 1; else hi = mid;
    }
    g_rowptr[i] = lo;
}

// ---------------------------------------------------------------------------
// Fused projection GEMM: {Q,K,V,S} = h @ W_m + b_m
// M=10000, N=128 per matrix, K=128. Block tile 128x128, BK=16, 256 threads,
// 8x8 microtile arranged as 2x2 blocks of 4x4 (conflict-free LDS.128).
// blockIdx.y = matrix index (0=Q,1=K,2=V,3=S).
// Q,S written fp32; K,V written bf16 (halves attention L2 traffic).
// ---------------------------------------------------------------------------
#define GBM 128
#define GBN 128
#define GBK 16

__global__ __launch_bounds__(256)
void gemm_qkvs_kernel(const float* __restrict__ xin,
                      const float* __restrict__ Wq, const float* __restrict__ Wk,
                      const float* __restrict__ Wv, const float* __restrict__ Ws,
                      const float* __restrict__ bq, const float* __restrict__ bk,
                      const float* __restrict__ bv, const float* __restrict__ bs,
                      int layer, int use_gh) {
    __shared__ float Asm[GBK][GBM + 4];
    __shared__ float Bsm[GBK][GBN];

    const float* A = use_gh ? g_h : xin;
    const int mtx = blockIdx.y;
    const float* W = (mtx == 0 ? Wq : mtx == 1 ? Wk : mtx == 2 ? Wv : Ws)
                     + (size_t)layer * DD * DD;
    const float* bias = (mtx == 0 ? bq : mtx == 1 ? bk : mtx == 2 ? bv : bs)
                        + layer * DD;
    const int rowbase = blockIdx.x * GBM;

    const int tid = threadIdx.x;
    const int tx = tid & 15;       // 16 col groups
    const int ty = tid >> 4;       // 16 row groups

    float acc[8][8];
    #pragma unroll
    for (int i = 0; i < 8; ++i)
        #pragma unroll
        for (int j = 0; j < 8; ++j) acc[i][j] = 0.f;

    for (int k0 = 0; k0 < DD; k0 += GBK) {
        // Load A tile 128x16 (transposed into Asm). 512 float4, 2 per thread.
        #pragma unroll
        for (int r = 0; r < 2; ++r) {
            int f = tid + r * 256;
            int row = f >> 2;          // 0..127
            int c4  = f & 3;           // 0..3  (k chunk of 4)
            int grow = rowbase + row;
            float4 v = make_float4(0.f, 0.f, 0.f, 0.f);
            if (grow < NN) v = *(const float4*)&A[(size_t)grow * DD + k0 + c4 * 4];
            Asm[c4 * 4 + 0][row] = v.x;
            Asm[c4 * 4 + 1][row] = v.y;
            Asm[c4 * 4 + 2][row] = v.z;
            Asm[c4 * 4 + 3][row] = v.w;
        }
        // Load B tile 16x128. 512 float4, 2 per thread, coalesced.
        #pragma unroll
        for (int r = 0; r < 2; ++r) {
            int f = tid + r * 256;
            int kk = f >> 5;           // 0..15
            int c4 = f & 31;           // 0..31
            *(float4*)&Bsm[kk][c4 * 4] =
                *(const float4*)&W[(size_t)(k0 + kk) * DD + c4 * 4];
        }
        __syncthreads();

        #pragma unroll
        for (int kk = 0; kk < GBK; ++kk) {
            float a[8], b[8];
            *(float4*)&a[0] = *(const float4*)&Asm[kk][ty * 4];
            *(float4*)&a[4] = *(const float4*)&Asm[kk][64 + ty * 4];
            *(float4*)&b[0] = *(const float4*)&Bsm[kk][tx * 4];
            *(float4*)&b[4] = *(const float4*)&Bsm[kk][64 + tx * 4];
            #pragma unroll
            for (int i = 0; i < 8; ++i)
                #pragma unroll
                for (int j = 0; j < 8; ++j)
                    acc[i][j] += a[i] * b[j];
        }
        __syncthreads();
    }

    // Epilogue
    float bv0[8];
    #pragma unroll
    for (int hc = 0; hc < 2; ++hc) {
        *(float4*)&bv0[hc * 4] = *(const float4*)&bias[hc * 64 + tx * 4];
    }

    #pragma unroll
    for (int hr = 0; hr < 2; ++hr) {
        #pragma unroll
        for (int i = 0; i < 4; ++i) {
            int grow = rowbase + hr * 64 + ty * 4 + i;
            if (grow >= NN) continue;
            int ri = hr * 4 + i;
            #pragma unroll
            for (int hc = 0; hc < 2; ++hc) {
                int cb = hc * 64 + tx * 4;
                float4 o;
                o.x = acc[ri][hc * 4 + 0] + bv0[hc * 4 + 0];
                o.y = acc[ri][hc * 4 + 1] + bv0[hc * 4 + 1];
                o.z = acc[ri][hc * 4 + 2] + bv0[hc * 4 + 2];
                o.w = acc[ri][hc * 4 + 3] + bv0[hc * 4 + 3];
                size_t off = (size_t)grow * DD + cb;
                if (mtx == 0) {
                    *(float4*)&g_qkvs[off] = o;
                } else if (mtx == 3) {
                    *(float4*)&g_qkvs[NDSZ + off] = o;
                } else {
                    __nv_bfloat162 p0 = __floats2bfloat162_rn(o.x, o.y);
                    __nv_bfloat162 p1 = __floats2bfloat162_rn(o.z, o.w);
                    __nv_bfloat16* dstp = (mtx == 1) ? g_kbf : g_vbf;
                    *(__nv_bfloat162*)&dstp[off]     = p0;
                    *(__nv_bfloat162*)&dstp[off + 2] = p1;
                }
            }
        }
    }
}

// ---------------------------------------------------------------------------
// Attention: one warp per destination node, online softmax over incoming edges.
// Graph is symmetric (undirected base + self loops; A^2 of symmetric is
// symmetric), so incoming neighbors of i = dst[e] for e in rowptr[i]..rowptr[i+1].
// Lane l holds dims [4l,4l+4); head = l>>2; head dot via shfl_xor(1),(2).
// K/V are bf16 (half the L2 traffic); Q/S/h fp32.
// mode 0: h = xin, out = g_h, ReLU.  mode 1: h = g_h, out = outp, no ReLU.
// ---------------------------------------------------------------------------
__device__ __forceinline__ float4 load_bf16x4(const __nv_bfloat16* p) {
    uint2 u = *(const uint2*)p;
    __nv_bfloat162 p0 = *(__nv_bfloat162*)&u.x;
    __nv_bfloat162 p1 = *(__nv_bfloat162*)&u.y;
    float2 f0 = __bfloat1622float2(p0);
    float2 f1 = __bfloat1622float2(p1);
    return make_float4(f0.x, f0.y, f1.x, f1.y);
}

__global__ __launch_bounds__(256)
void attn_kernel(const float* __restrict__ xin,
                 const int* __restrict__ nbr,
                 float* __restrict__ outp, int mode) {
    int gwarp = (blockIdx.x * blockDim.x + threadIdx.x) >> 5;
    if (gwarp >= NN) return;
    const int lane = threadIdx.x & 31;
    const int i = gwarp;

    const float* Q = g_qkvs;
    const float* S = g_qkvs + NDSZ;
    const float* h = mode ? g_h : xin;

    // load q and fold in 1/sqrt(C) = 0.25
    float4 q4 = *(const float4*)&Q[(size_t)i * DD + lane * 4];
    q4.x *= 0.25f; q4.y *= 0.25f; q4.z *= 0.25f; q4.w *= 0.25f;

    float m = -1e30f;
    float z = 0.f;
    float4 acc = make_float4(0.f, 0.f, 0.f, 0.f);

    const int e0 = g_rowptr[i];
    const int e1 = g_rowptr[i + 1];

    int j = (e0 < e1) ? nbr[e0] : 0;
    for (int e = e0; e < e1; ++e) {
        int jn = (e + 1 < e1) ? nbr[e + 1] : 0;
        float4 k4 = load_bf16x4(&g_kbf[(size_t)j * DD + lane * 4]);
        float4 v4 = load_bf16x4(&g_vbf[(size_t)j * DD + lane * 4]);
        float d = q4.x * k4.x + q4.y * k4.y + q4.z * k4.z + q4.w * k4.w;
        d += __shfl_xor_sync(0xFFFFFFFFu, d, 1);
        d += __shfl_xor_sync(0xFFFFFFFFu, d, 2);

        float nm = fmaxf(m, d);
        float scale = __expf(m - nm);    // 0 on first edge (m=-1e30)
        float p = __expf(d - nm);
        z = z * scale + p;

        acc.x = acc.x * scale + p * v4.x;
        acc.y = acc.y * scale + p * v4.y;
        acc.z = acc.z * scale + p * v4.z;
        acc.w = acc.w * scale + p * v4.w;
        m = nm;
        j = jn;
    }

    float inv = 1.f / z;
    float4 h4 = *(const float4*)&h[(size_t)i * DD + lane * 4];
    float4 s4 = *(const float4*)&S[(size_t)i * DD + lane * 4];
    float4 o;
    o.x = acc.x * inv + h4.x + s4.x;
    o.y = acc.y * inv + h4.y + s4.y;
    o.z = acc.z * inv + h4.z + s4.z;
    o.w = acc.w * inv + h4.w + s4.w;

    if (mode == 0) {
        o.x = fmaxf(o.x, 0.f); o.y = fmaxf(o.y, 0.f);
        o.z = fmaxf(o.z, 0.f); o.w = fmaxf(o.w, 0.f);
        *(float4*)&g_h[(size_t)i * DD + lane * 4] = o;
    } else {
        *(float4*)&outp[(size_t)i * DD + lane * 4] = o;
    }
}

// ---------------------------------------------------------------------------
// Launch — only kernel launches.
// Inputs: 0=x 1=Wq 2=bq 3=Wk 4=bk 5=Wv 6=bv 7=Ws 8=bs 9=attn_window[2,E] int32
// ---------------------------------------------------------------------------
extern "C" void kernel_launch(void* const* d_in, const int* in_sizes, int n_in,
                              void* d_out, int out_size) {
    const float* x  = (const float*)d_in[0];
    const float* Wq = (const float*)d_in[1];
    const float* bq = (const float*)d_in[2];
    const float* Wk = (const float*)d_in[3];
    const float* bk = (const float*)d_in[4];
    const float* Wv = (const float*)d_in[5];
    const float* bv = (const float*)d_in[6];
    const float* Ws = (const float*)d_in[7];
    const float* bs = (const float*)d_in[8];
    const int*   aw = (const int*)d_in[9];
    const int E = in_sizes[9] / 2;
    const int* src = aw;
    const int* dst = aw + E;

    build_rowptr_kernel<<<(NN + 256) / 256, 256>>>(src, E);

    dim3 ggrid((NN + GBM - 1) / GBM, 4);
    dim3 agrid((NN * 32 + 255) / 256);

    // Layer 0
    gemm_qkvs_kernel<<<ggrid, 256>>>(x, Wq, Wk, Wv, Ws, bq, bk, bv, bs, 0, 0);
    attn_kernel<<<agrid, 256>>>(x, dst, nullptr, 0);

    // Layer 1
    gemm_qkvs_kernel<<<ggrid, 256>>>(x, Wq, Wk, Wv, Ws, bq, bk, bv, bs, 1, 1);
    attn_kernel<<<agrid, 256>>>(nullptr, dst, (float*)d_out, 1);
}